// round 9
// baseline (speedup 1.0000x reference)
#include <cuda_runtime.h>
#include <cstdint>

// GIKDWConv: depthwise 7x7 conv, stride 1, pad 3, 4-fold-rotation-symmetrized
// weights. N=16, C=384, H=W=64, fp32.
//
// R9: persistent grid (740 = 148 SMs x 5 CTAs) over 6144 half-tile items
// (tail 8.3 -> ~8% vs 20% for 3072 blocks), combined with R8's interleaved
// cp.async slice prefetch: item i+1's tile + raw weights stream in INSIDE
// item i's FMA loop (2 slices per row iteration), never as a burst.
// Compute core unchanged: 8 rows x 2 cols per thread, channel pairs packed
// in f32x2 (fma.rn.f32x2), 13 unique symmetrized weights in registers.

#define HH 64
#define WW 64
#define NN 16
#define CC 384
#define TR 38              // tile rows: 32 output + 6 halo
#define TC 70              // tile cols: 64 output + 6 halo
#define CELLS (TR * TC)    // 2660
#define NSLICE 21          // ceil(2660/128)
#define RPT 8              // output rows per thread
#define ITEMS 6144         // 3072 (n,cp) pairs x 2 vertical halves
#define NBLK 740           // 148 SMs x 5 CTAs
typedef unsigned long long ull;

// orbit id of each (ky,kx) tap under 90-degree rotation (13 unique weights)
__device__ constexpr int ORBIT[7][7] = {
    {0, 1, 2, 3, 4, 5, 0},
    {5, 6, 7, 8, 9, 6, 1},
    {4, 9,10,11,10, 7, 2},
    {3, 8,11,12,11, 8, 3},
    {2, 7,10,11,10, 9, 4},
    {1, 6, 9, 8, 7, 6, 5},
    {0, 5, 4, 3, 2, 1, 0}};
__device__ constexpr int REP_I[13] = {0,0,0,0,0,0,1,1,1,1,2,2,3};
__device__ constexpr int REP_J[13] = {0,1,2,3,4,5,1,2,3,4,2,3,3};

__device__ __forceinline__ ull fma2(ull a, ull b, ull c) {
    ull d;
    asm("fma.rn.f32x2 %0, %1, %2, %3;" : "=l"(d) : "l"(a), "l"(b), "l"(c));
    return d;
}
__device__ __forceinline__ ull pack2(float lo, float hi) {
    ull r;
    asm("mov.b64 %0, {%1, %2};" : "=l"(r) : "f"(lo), "f"(hi));
    return r;
}
__device__ __forceinline__ void unpack2(ull v, float& lo, float& hi) {
    asm("mov.b64 {%0, %1}, %2;" : "=f"(lo), "=f"(hi) : "l"(v));
}
__device__ __forceinline__ uint32_t s2u(const void* p) {
    uint32_t a;
    asm("{ .reg .u64 t; cvta.to.shared.u64 t, %1; cvt.u32.u64 %0, t; }"
        : "=r"(a) : "l"(p));
    return a;
}
// 4-byte cp.async with zfill: sz=4 copies, sz=0 writes zeros (no src access)
__device__ __forceinline__ void cp4(uint32_t d, const float* s, int sz) {
    asm volatile("cp.async.ca.shared.global [%0], [%1], 4, %2;"
                 :: "r"(d), "l"(s), "r"(sz));
}
__device__ __forceinline__ void cp8(uint32_t d, const float* s) {
    asm volatile("cp.async.ca.shared.global [%0], [%1], 8;"
                 :: "r"(d), "l"(s));
}

struct Buf {
    ull   sx[CELLS];   // packed (c0,c1) half-tile
    float wraw[100];   // raw weights: c0[49], c1[49] (+pad)
};

__global__ __launch_bounds__(128, 5)
void gik_dwconv_kernel(const float* __restrict__ x,
                       const float* __restrict__ weight,
                       float* __restrict__ out) {
    __shared__ Buf buf[2];          // 2 x ~21.7 KB
    __shared__ ull swsym[2][13];    // symmetrized packed weights per buffer

    const int tid = threadIdx.x;

    // one 128-cell cp.async slice of item tile (gy0 = first global row)
    auto slice = [&](int s, const float* x0, const float* x1,
                     uint32_t dst0, int gy0) {
        int cell = s * 128 + tid;
        if (cell < CELLS) {
            int r  = cell / TC;
            int c  = cell - r * TC;
            int gy = gy0 + r, gx = c - 3;
            int v  = ((unsigned)gy < (unsigned)HH) &
                     ((unsigned)gx < (unsigned)WW);
            int off = v ? (gy * WW + gx) : 0;
            int sz  = v ? 4 : 0;
            cp4(dst0 + cell * 8,     x0 + off, sz);
            cp4(dst0 + cell * 8 + 4, x1 + off, sz);
        }
    };

    // ---- prologue: fully load first item into buffer 0 ----
    {
        const int id = blockIdx.x;
        const int t  = id & 1;
        const int pc = id >> 1;
        const int n  = pc / 192;
        const int cp = pc - n * 192;
        const float* x0 = x + ((n * CC + cp * 2) * (HH * WW));
        const float* x1 = x0 + HH * WW;
        const uint32_t d0 = s2u(buf[0].sx);
        const int gy0 = t * 32 - 3;
        #pragma unroll
        for (int s = 0; s < NSLICE; s++) slice(s, x0, x1, d0, gy0);
        if (tid < 49)
            cp8(s2u(buf[0].wraw) + tid * 8, weight + cp * 98 + tid * 2);
        asm volatile("cp.async.commit_group;" ::: "memory");
    }

    const int cx = (tid & 31) * 2;     // even output column 0..62
    const int r0 = (tid >> 5) * RPT;   // local output row base: 0,8,16,24

    int b = 0;
    for (int id = blockIdx.x; id < ITEMS; id += NBLK) {
        asm volatile("cp.async.wait_group 0;" ::: "memory");
        __syncthreads();               // tile + raw weights of item id ready

        // symmetrize weights for this item (reads buf[b].wraw)
        if (tid < 13) {
            const int i = REP_I[tid], j = REP_J[tid];
            const float* w0 = buf[b].wraw;
            const float* w1 = w0 + 49;
            float a0 = 0.25f * (w0[i*7 + j] + w0[j*7 + (6-i)] +
                                w0[(6-i)*7 + (6-j)] + w0[(6-j)*7 + i]);
            float a1 = 0.25f * (w1[i*7 + j] + w1[j*7 + (6-i)] +
                                w1[(6-i)*7 + (6-j)] + w1[(6-j)*7 + i]);
            swsym[b][tid] = pack2(a0, a1);
        }
        __syncthreads();

        ull wreg[13];
        #pragma unroll
        for (int o = 0; o < 13; o++) wreg[o] = swsym[b][o];

        // decode next item (prefetch targets)
        const int nid = id + NBLK;
        const bool hn = nid < ITEMS;
        const float *nx0 = x, *nx1 = x;
        const float *nwp = weight;
        uint32_t nd0 = 0;
        int ngy0 = 0;
        if (hn) {
            const int t  = nid & 1;
            const int pc = nid >> 1;
            const int n  = pc / 192;
            const int cp = pc - n * 192;
            nx0  = x + ((n * CC + cp * 2) * (HH * WW));
            nx1  = nx0 + HH * WW;
            nwp  = weight + cp * 98;
            nd0  = s2u(buf[b ^ 1].sx);
            ngy0 = t * 32 - 3;
        }

        ull acc0[RPT], acc1[RPT];      // col cx and cx+1
        #pragma unroll
        for (int r = 0; r < RPT; r++) { acc0[r] = 0ull; acc1[r] = 0ull; }

        const ull* sb = buf[b].sx;
        #pragma unroll
        for (int y = 0; y < RPT + 6; y++) {
            ull xv[8];                 // 8 packed inputs: 4x LDS.128
            {
                const ulonglong2* rp =
                    (const ulonglong2*)(sb + (r0 + y) * TC + cx);
                #pragma unroll
                for (int q = 0; q < 4; q++) {
                    ulonglong2 v = rp[q];
                    xv[2*q] = v.x; xv[2*q+1] = v.y;
                }
            }
            // interleaved prefetch of next item (slices y and y+14)
            if (hn) {
                slice(y, nx0, nx1, nd0, ngy0);
                if (y < NSLICE - 14) slice(y + 14, nx0, nx1, nd0, ngy0);
                if (y == 0 && tid < 49)
                    cp8(s2u(buf[b ^ 1].wraw) + tid * 8, nwp + tid * 2);
            }
            #pragma unroll
            for (int k = 0; k < 7; k++) {
                const int r = y - k;
                if (r >= 0 && r < RPT) {
                    #pragma unroll
                    for (int u = 0; u < 7; u++) {
                        const ull w = wreg[ORBIT[k][u]];
                        acc0[r] = fma2(w, xv[u],     acc0[r]);
                        acc1[r] = fma2(w, xv[u + 1], acc1[r]);
                    }
                }
            }
        }
        if (hn)
            asm volatile("cp.async.commit_group;" ::: "memory");

        // ---- store: float2 per channel-row ----
        {
            const int t  = id & 1;
            const int pc = id >> 1;
            const int n  = pc / 192;
            const int cp = pc - n * 192;
            float* o0 = out + ((n * CC + cp * 2) * (HH * WW)) + t * 32 * WW;
            float* o1 = o0 + HH * WW;
            #pragma unroll
            for (int r = 0; r < RPT; r++) {
                float a, bb, c, d;
                unpack2(acc0[r], a, bb);   // a: c0 col cx,   bb: c1 col cx
                unpack2(acc1[r], c, d);    // c: c0 col cx+1, d: c1 col cx+1
                const int off = (r0 + r) * WW + cx;
                *(float2*)(o0 + off) = make_float2(a, c);
                *(float2*)(o1 + off) = make_float2(bb, d);
            }
        }
        b ^= 1;
    }
}

extern "C" void kernel_launch(void* const* d_in, const int* in_sizes, int n_in,
                              void* d_out, int out_size) {
    const float* x = (const float*)d_in[0];       // [16,384,64,64]
    const float* w = (const float*)d_in[1];       // [384,1,7,7]
    float* out = (float*)d_out;                   // [16,384,64,64]
    gik_dwconv_kernel<<<NBLK, 128>>>(x, w, out);
}